// round 1
// baseline (speedup 1.0000x reference)
#include <cuda_runtime.h>
#include <cuda_bf16.h>

#define D_DIM 256
#define MAX_C 2048
#define MAX_N 32768

// Scratch (static __device__ globals — no allocation allowed in kernel_launch)
__device__ float g_embed[MAX_C * D_DIM];    // [K, D] row-major (for gather)
__device__ float g_embedT[D_DIM * MAX_C];   // [D, K] transposed (for GEMM loads)
__device__ float g_esq[MAX_C];              // ||e_k||^2
__device__ int   g_ind[MAX_N];              // argmin indices

// ---------------------------------------------------------------------------
// Kernel 1: embed = embed_sum / max(usage, eps); write row-major + transposed;
// reduce ||e||^2 per code. One block per code, 256 threads (one per d).
// ---------------------------------------------------------------------------
__global__ void prep_kernel(const float* __restrict__ embed_sum,
                            const float* __restrict__ usage, int C) {
    int k = blockIdx.x;
    int d = threadIdx.x;
    float u = fmaxf(usage[k], 1e-5f);
    float v = embed_sum[k * D_DIM + d] / u;   // IEEE divide, matches reference
    g_embed[k * D_DIM + d] = v;
    g_embedT[d * C + k]    = v;

    __shared__ float red[256];
    red[d] = v * v;
    __syncthreads();
    #pragma unroll
    for (int s = 128; s > 0; s >>= 1) {
        if (d < s) red[d] += red[d + s];
        __syncthreads();
    }
    if (d == 0) g_esq[k] = red[0];
}

// ---------------------------------------------------------------------------
// Kernel 2: fused GEMM + argmin.
// Block tile: 64 tokens x 128 codes, threads 16x16, per-thread 4 tokens x 8 codes.
// D reduced in chunks of 16 through shared memory.
// dist = ||e||^2 - 2 * (x . e)   (x^2 dropped — argmin-invariant)
// ---------------------------------------------------------------------------
__global__ __launch_bounds__(256) void argmin_kernel(const float* __restrict__ X,
                                                     int N, int C) {
    __shared__ float Xs[16][68];    // [d][token], padded
    __shared__ float Es[16][132];   // [d][code],  padded

    int tid = threadIdx.x;
    int tx = tid & 15;      // code group
    int ty = tid >> 4;      // token group
    int row0 = blockIdx.x * 64;

    float best[4];
    int   bestI[4];
    #pragma unroll
    for (int i = 0; i < 4; i++) { best[i] = 3.4e38f; bestI[i] = 0; }

    int xtok = tid >> 2;            // 0..63 token within tile
    int xdv  = (tid & 3) * 4;       // 0,4,8,12 d-offset within chunk

    for (int c0 = 0; c0 < C; c0 += 128) {
        float acc[4][8];
        #pragma unroll
        for (int i = 0; i < 4; i++)
            #pragma unroll
            for (int j = 0; j < 8; j++) acc[i][j] = 0.f;

        for (int d0 = 0; d0 < D_DIM; d0 += 16) {
            __syncthreads();
            // load X tile (64 tokens x 16 d), transposed into Xs: 1 float4/thread
            {
                float4 x4 = *(const float4*)&X[(size_t)(row0 + xtok) * D_DIM + d0 + xdv];
                Xs[xdv + 0][xtok] = x4.x;
                Xs[xdv + 1][xtok] = x4.y;
                Xs[xdv + 2][xtok] = x4.z;
                Xs[xdv + 3][xtok] = x4.w;
            }
            // load E tile (16 d x 128 codes) from transposed embed: 2 float4/thread
            #pragma unroll
            for (int r = 0; r < 2; r++) {
                int idx = tid + r * 256;
                int dd = idx >> 5;            // 0..15
                int cv = (idx & 31) * 4;      // 0..124
                *(float4*)&Es[dd][cv] =
                    *(const float4*)&g_embedT[(size_t)(d0 + dd) * C + c0 + cv];
            }
            __syncthreads();

            #pragma unroll
            for (int dd = 0; dd < 16; dd++) {
                float4 a  = *(const float4*)&Xs[dd][ty * 4];
                float4 b0 = *(const float4*)&Es[dd][tx * 8];
                float4 b1 = *(const float4*)&Es[dd][tx * 8 + 4];
                float av[4] = {a.x, a.y, a.z, a.w};
                float bv[8] = {b0.x, b0.y, b0.z, b0.w, b1.x, b1.y, b1.z, b1.w};
                #pragma unroll
                for (int i = 0; i < 4; i++)
                    #pragma unroll
                    for (int j = 0; j < 8; j++)
                        acc[i][j] = fmaf(av[i], bv[j], acc[i][j]);
            }
        }

        // fold this 128-code chunk into running argmin (codes ascending in j
        // and ascending chunks + strict < => first-min tie-breaking)
        #pragma unroll
        for (int j = 0; j < 8; j++) {
            int code = c0 + tx * 8 + j;
            float e = g_esq[code];
            #pragma unroll
            for (int i = 0; i < 4; i++) {
                float dist = fmaf(-2.f, acc[i][j], e);
                if (dist < best[i]) { best[i] = dist; bestI[i] = code; }
            }
        }
    }

    // reduce across the 16 tx-threads sharing each token (width-16 shuffle)
    #pragma unroll
    for (int i = 0; i < 4; i++) {
        float b = best[i];
        int bi = bestI[i];
        #pragma unroll
        for (int off = 8; off > 0; off >>= 1) {
            float ob  = __shfl_down_sync(0xffffffffu, b,  off, 16);
            int   obi = __shfl_down_sync(0xffffffffu, bi, off, 16);
            if (ob < b || (ob == b && obi < bi)) { b = ob; bi = obi; }
        }
        if (tx == 0) g_ind[row0 + ty * 4 + i] = bi;
    }
}

// ---------------------------------------------------------------------------
// Kernel 3: quantize[n] = embed[ind[n]]; indices appended (as float) after
// the quantize block. 1 block per token, 64 threads, float4 each.
// ---------------------------------------------------------------------------
__global__ void gather_kernel(float* __restrict__ out, int N) {
    int n = blockIdx.x;
    int t = threadIdx.x;
    int idx = g_ind[n];
    float4 v = *(const float4*)&g_embed[(size_t)idx * D_DIM + t * 4];
    *(float4*)&out[(size_t)n * D_DIM + t * 4] = v;
    if (t == 0) out[(size_t)N * D_DIM + n] = (float)idx;
}

// ---------------------------------------------------------------------------
extern "C" void kernel_launch(void* const* d_in, const int* in_sizes, int n_in,
                              void* d_out, int out_size) {
    const float* X  = (const float*)d_in[0];  // hidden_states [B*T*D]
    const float* ES = (const float*)d_in[1];  // embed_sum [K*D]
    const float* U  = (const float*)d_in[2];  // cluster_usage [K]
    float* out = (float*)d_out;

    int C = in_sizes[2];            // 2048
    int N = in_sizes[0] / D_DIM;    // 32768

    prep_kernel<<<C, 256>>>(ES, U, C);
    argmin_kernel<<<N / 64, 256>>>(X, N, C);
    gather_kernel<<<N, 64>>>(out, N);
}

// round 3
// speedup vs baseline: 2.3946x; 2.3946x over previous
#include <cuda_runtime.h>
#include <cuda_bf16.h>
#include <cstdint>

#define D_DIM 256
#define N_TOK 32768
#define N_CODE 2048

// ---------------- scratch (static device globals) ---------------------------
__device__ float g_xhi[N_TOK * D_DIM];   // X hi split, mma-fragment-ordered
__device__ float g_xlo[N_TOK * D_DIM];   // X lo split
__device__ float g_ehi[N_CODE * D_DIM];  // E hi split, fragment-ordered
__device__ float g_elo[N_CODE * D_DIM];  // E lo split
__device__ float g_embed[N_CODE * D_DIM];// E row-major (gather)
__device__ float g_esq[N_CODE];          // ||e||^2
__device__ int   g_ind[N_TOK];

// ---------------- helpers ----------------------------------------------------
__device__ __forceinline__ uint32_t smem_u32(const void* p) {
    uint32_t a;
    asm("{ .reg .u64 t; cvta.to.shared.u64 t, %1; cvt.u32.u64 %0, t; }"
        : "=r"(a) : "l"(p));
    return a;
}
__device__ __forceinline__ float tf32_rna(float x) {
    uint32_t u;
    asm("cvt.rna.tf32.f32 %0, %1;" : "=r"(u) : "f"(x));
    return __uint_as_float(u);
}

#define MBAR_INIT(a, c) asm volatile("mbarrier.init.shared.b64 [%0], %1;" :: "r"(a), "r"((uint32_t)(c)) : "memory")
#define MBAR_EXPECT_TX(a, b) asm volatile("mbarrier.arrive.expect_tx.shared.b64 _, [%0], %1;" :: "r"(a), "r"((uint32_t)(b)) : "memory")
#define MBAR_ARRIVE(a)  asm volatile("mbarrier.arrive.shared.b64 _, [%0];" :: "r"(a) : "memory")

#define MBAR_WAIT(mbar, parity) do {                                          \
    uint32_t _m = (mbar), _ph = (parity), _done;                              \
    asm volatile("{ .reg .pred p; mbarrier.try_wait.parity.acquire.cta.shared::cta.b64 p, [%1], %2; selp.b32 %0, 1, 0, p; }" \
                 : "=r"(_done) : "r"(_m), "r"(_ph) : "memory");               \
    if (!_done) {                                                             \
        asm volatile("{ .reg .pred P1; WL_%=: mbarrier.try_wait.parity.acquire.cta.shared::cta.b64 P1, [%0], %1, 0x989680; @P1 bra.uni WD_%=; bra.uni WL_%=; WD_%=: }" \
                     :: "r"(_m), "r"(_ph) : "memory");                        \
    }                                                                         \
} while (0)

#define BULK_G2S(dst, src, bytes, mbar)                                       \
    asm volatile("cp.async.bulk.shared::cluster.global.mbarrier::complete_tx::bytes [%0], [%1], %2, [%3];" \
                 :: "r"(dst), "l"(src), "r"((uint32_t)(bytes)), "r"(mbar) : "memory")

// mma.sync m16n8k8 tf32: d += a*b (fp32 accumulate)
__device__ __forceinline__ void mma_tf32(float* d, const uint32_t* a, const uint32_t* b) {
    asm("mma.sync.aligned.m16n8k8.row.col.f32.tf32.tf32.f32 "
        "{%0,%1,%2,%3}, {%4,%5,%6,%7}, {%8,%9}, {%0,%1,%2,%3};"
        : "+f"(d[0]), "+f"(d[1]), "+f"(d[2]), "+f"(d[3])
        : "r"(a[0]), "r"(a[1]), "r"(a[2]), "r"(a[3]), "r"(b[0]), "r"(b[1]));
}

// ---------------------------------------------------------------------------
// prep_e: embed = embed_sum / max(u,eps); row-major copy, esq, and tf32 split
// written in B-fragment order:
//   idx = (pass*8+chunk)*4096 + ((ks*16 + n_tile)*32 + lane)*2 + reg
//   lane = ncol*4 + (krow&3),  reg = krow>>2
// ---------------------------------------------------------------------------
__global__ void prep_e_kernel(const float* __restrict__ embed_sum,
                              const float* __restrict__ usage) {
    int k = blockIdx.x, d = threadIdx.x;
    float u = fmaxf(usage[k], 1e-5f);
    float v = embed_sum[k * D_DIM + d] / u;
    g_embed[k * D_DIM + d] = v;

    float hi = tf32_rna(v);
    float lo = tf32_rna(v - hi);

    int pass = k >> 7, n_in = k & 127;
    int n_tile = n_in >> 3, ncol = n_in & 7;
    int chunk = d >> 5, kk = d & 31, ks = kk >> 3, krow = kk & 7;
    int lane = ncol * 4 + (krow & 3);
    int reg = krow >> 2;
    int idx = (pass * 8 + chunk) * 4096 + ((ks * 16 + n_tile) * 32 + lane) * 2 + reg;
    g_ehi[idx] = hi;
    g_elo[idx] = lo;

    __shared__ float red[256];
    red[d] = v * v;
    __syncthreads();
    #pragma unroll
    for (int s = 128; s > 0; s >>= 1) {
        if (d < s) red[d] += red[d + s];
        __syncthreads();
    }
    if (d == 0) g_esq[k] = red[0];
}

// ---------------------------------------------------------------------------
// split_x: tf32 split of X written in A-fragment order:
//   idx = (m_block*8+chunk)*4096 + ((ks*8 + m_tile)*32 + lane)*4 + reg
//   lane = g*4 + (kc&3),  reg = (r>>3) | ((kc>>2)<<1),  g = r&7
// ---------------------------------------------------------------------------
__global__ void split_x_kernel(const float* __restrict__ X) {
    int i4 = blockIdx.x * blockDim.x + threadIdx.x;   // float4 index
    int n = i4 >> 6;            // token
    int d0 = (i4 & 63) * 4;     // first d of the 4
    float4 x = ((const float4*)X)[i4];
    float xv[4] = {x.x, x.y, x.z, x.w};

    int m_block = n >> 7, m_in = n & 127;
    int m_tile = m_in >> 4, r = m_in & 15;
    int gg = r & 7, rh = r >> 3;

    #pragma unroll
    for (int j = 0; j < 4; ++j) {
        int d = d0 + j;
        float hi = tf32_rna(xv[j]);
        float lo = tf32_rna(xv[j] - hi);
        int chunk = d >> 5, kk = d & 31, ks = kk >> 3, kc = kk & 7;
        int lane = gg * 4 + (kc & 3);
        int reg = rh | ((kc >> 2) << 1);
        int idx = (m_block * 8 + chunk) * 4096 + ((ks * 8 + m_tile) * 32 + lane) * 4 + reg;
        g_xhi[idx] = hi;
        g_xlo[idx] = lo;
    }
}

// ---------------------------------------------------------------------------
// Fused tf32x2 mma.sync GEMM + argmin.
// 256 threads = 8 warps (4m x 2n). CTA tile: 128 tokens x 128 codes/pass,
// 16 passes, K=256 in 8 chunks of 32, 3-stage cp.async.bulk pipeline.
// SMEM: [0..48) mbarriers | [1024..9216) esq | [9216..11264) candidates |
//       [16384 + s*65536) stage s: A_hi 16K | A_lo 16K | B_hi 16K | B_lo 16K
// ---------------------------------------------------------------------------
#define SMEM_TOTAL (16384 + 3 * 65536)

__global__ void __launch_bounds__(256, 1) argmin_mma_kernel() {
    extern __shared__ __align__(1024) char smem[];
    uint32_t sb = smem_u32(smem);
    int tid = threadIdx.x, lane = tid & 31, wid = tid >> 5;
    int warp_m = wid & 3, warp_n = wid >> 2;

    const uint32_t FB[3] = {sb + 0,  sb + 8,  sb + 16};
    const uint32_t EB[3] = {sb + 24, sb + 32, sb + 40};
    float* esq_s = (float*)(smem + 1024);
    float* candD = (float*)(smem + 9216);            // [2][128]
    int*   candI = (int*)(smem + 9216 + 1024);       // [2][128]

    if (tid == 0) {
        #pragma unroll
        for (int s = 0; s < 3; ++s) { MBAR_INIT(FB[s], 1); MBAR_INIT(EB[s], 256); }
    }
    for (int i = tid; i < N_CODE; i += 256) esq_s[i] = g_esq[i];
    __syncthreads();

    // prologue: fill 3 stages
    if (tid == 0) {
        #pragma unroll
        for (int g = 0; g < 3; ++g) {
            int s = g, pass = g >> 3, ch = g & 7;
            uint32_t st = sb + 16384 + s * 65536;
            MBAR_EXPECT_TX(FB[s], 65536);
            BULK_G2S(st,         &g_xhi[(blockIdx.x * 8 + ch) * 4096], 16384, FB[s]);
            BULK_G2S(st + 16384, &g_xlo[(blockIdx.x * 8 + ch) * 4096], 16384, FB[s]);
            BULK_G2S(st + 32768, &g_ehi[(pass * 8 + ch) * 4096], 16384, FB[s]);
            BULK_G2S(st + 49152, &g_elo[(pass * 8 + ch) * 4096], 16384, FB[s]);
        }
    }

    float best[2][2];
    int bestI[2][2];
    #pragma unroll
    for (int a = 0; a < 2; ++a)
        #pragma unroll
        for (int b = 0; b < 2; ++b) { best[a][b] = 3.4e38f; bestI[a][b] = 0; }

    int row0 = blockIdx.x * 128;
    int t4 = lane & 3, g4 = lane >> 2;

    #pragma unroll 1
    for (int pass = 0; pass < 16; ++pass) {
        float acc[2][8][4];
        #pragma unroll
        for (int mt = 0; mt < 2; ++mt)
            #pragma unroll
            for (int nt = 0; nt < 8; ++nt)
                #pragma unroll
                for (int j = 0; j < 4; ++j) acc[mt][nt][j] = 0.f;

        #pragma unroll 1
        for (int ch = 0; ch < 8; ++ch) {
            int g = pass * 8 + ch;
            int s = g % 3, k3 = g / 3;
            MBAR_WAIT(FB[s], k3 & 1);

            const char* stg = smem + 16384 + s * 65536;
            const char* Ah = stg;
            const char* Al = stg + 16384;
            const char* Bh = stg + 32768;
            const char* Bl = stg + 49152;

            #pragma unroll
            for (int ks = 0; ks < 4; ++ks) {
                uint32_t ah[2][4], al[2][4];
                #pragma unroll
                for (int mt = 0; mt < 2; ++mt) {
                    int off = ((ks * 8 + warp_m * 2 + mt) * 32 + lane) * 16;
                    *(uint4*)ah[mt] = *(const uint4*)(Ah + off);
                    *(uint4*)al[mt] = *(const uint4*)(Al + off);
                }
                uint32_t bh[8][2], bl[8][2];
                #pragma unroll
                for (int nt = 0; nt < 8; ++nt) {
                    int off = ((ks * 16 + warp_n * 8 + nt) * 32 + lane) * 8;
                    *(uint2*)bh[nt] = *(const uint2*)(Bh + off);
                    *(uint2*)bl[nt] = *(const uint2*)(Bl + off);
                }
                // term-ordered for ILP: hi*hi, hi*lo, lo*hi
                #pragma unroll
                for (int mt = 0; mt < 2; ++mt)
                    #pragma unroll
                    for (int nt = 0; nt < 8; ++nt)
                        mma_tf32(acc[mt][nt], ah[mt], bh[nt]);
                #pragma unroll
                for (int mt = 0; mt < 2; ++mt)
                    #pragma unroll
                    for (int nt = 0; nt < 8; ++nt)
                        mma_tf32(acc[mt][nt], ah[mt], bl[nt]);
                #pragma unroll
                for (int mt = 0; mt < 2; ++mt)
                    #pragma unroll
                    for (int nt = 0; nt < 8; ++nt)
                        mma_tf32(acc[mt][nt], al[mt], bh[nt]);
            }

            MBAR_ARRIVE(EB[s]);
            if (tid == 0 && g + 3 < 128) {
                MBAR_WAIT(EB[s], k3 & 1);     // wait all 256 consumed stage
                int gn = g + 3, pn = gn >> 3, cn = gn & 7;
                uint32_t st = sb + 16384 + s * 65536;
                MBAR_EXPECT_TX(FB[s], 65536);
                BULK_G2S(st,         &g_xhi[(blockIdx.x * 8 + cn) * 4096], 16384, FB[s]);
                BULK_G2S(st + 16384, &g_xlo[(blockIdx.x * 8 + cn) * 4096], 16384, FB[s]);
                BULK_G2S(st + 32768, &g_ehi[(pn * 8 + cn) * 4096], 16384, FB[s]);
                BULK_G2S(st + 49152, &g_elo[(pn * 8 + cn) * 4096], 16384, FB[s]);
            }
        }

        // fold pass into running argmin: dist = esq - 2*dot
        #pragma unroll
        for (int nt = 0; nt < 8; ++nt) {
            int cbase = pass * 128 + warp_n * 64 + nt * 8 + 2 * t4;
            float e0 = esq_s[cbase], e1 = esq_s[cbase + 1];
            #pragma unroll
            for (int mt = 0; mt < 2; ++mt) {
                float d0 = fmaf(-2.f, acc[mt][nt][0], e0);
                if (d0 < best[mt][0]) { best[mt][0] = d0; bestI[mt][0] = cbase; }
                float d1 = fmaf(-2.f, acc[mt][nt][1], e1);
                if (d1 < best[mt][0]) { best[mt][0] = d1; bestI[mt][0] = cbase + 1; }
                float d2 = fmaf(-2.f, acc[mt][nt][2], e0);
                if (d2 < best[mt][1]) { best[mt][1] = d2; bestI[mt][1] = cbase; }
                float d3 = fmaf(-2.f, acc[mt][nt][3], e1);
                if (d3 < best[mt][1]) { best[mt][1] = d3; bestI[mt][1] = cbase + 1; }
            }
        }
    }

    // reduce across the 4 lanes sharing each row (width-4 shuffle)
    #pragma unroll
    for (int mt = 0; mt < 2; ++mt)
        #pragma unroll
        for (int h = 0; h < 2; ++h) {
            float b = best[mt][h];
            int bi = bestI[mt][h];
            #pragma unroll
            for (int off = 2; off > 0; off >>= 1) {
                float ob = __shfl_down_sync(0xffffffffu, b, off, 4);
                int obi = __shfl_down_sync(0xffffffffu, bi, off, 4);
                if (ob < b || (ob == b && obi < bi)) { b = ob; bi = obi; }
            }
            if (t4 == 0) {
                int tok = warp_m * 32 + mt * 16 + g4 + 8 * h;
                candD[warp_n * 128 + tok] = b;
                candI[warp_n * 128 + tok] = bi;
            }
        }
    __syncthreads();

    if (tid < 128) {
        float b0 = candD[tid], b1 = candD[128 + tid];
        int i0 = candI[tid], i1 = candI[128 + tid];
        int sel = (b1 < b0 || (b1 == b0 && i1 < i0)) ? i1 : i0;
        g_ind[row0 + tid] = sel;
    }
}

// ---------------------------------------------------------------------------
__global__ void gather_kernel(float* __restrict__ out, int N) {
    int n = blockIdx.x, t = threadIdx.x;
    int idx = g_ind[n];
    float4 v = *(const float4*)&g_embed[(size_t)idx * D_DIM + t * 4];
    *(float4*)&out[(size_t)n * D_DIM + t * 4] = v;
    if (t == 0) out[(size_t)N * D_DIM + n] = (float)idx;
}

// ---------------------------------------------------------------------------
extern "C" void kernel_launch(void* const* d_in, const int* in_sizes, int n_in,
                              void* d_out, int out_size) {
    const float* X  = (const float*)d_in[0];
    const float* ES = (const float*)d_in[1];
    const float* U  = (const float*)d_in[2];
    float* out = (float*)d_out;
    (void)n_in; (void)out_size;
    int N = in_sizes[0] / D_DIM;   // 32768

    cudaFuncSetAttribute(argmin_mma_kernel,
                         cudaFuncAttributeMaxDynamicSharedMemorySize, SMEM_TOTAL);

    prep_e_kernel<<<N_CODE, 256>>>(ES, U);
    split_x_kernel<<<(N * D_DIM / 4) / 256, 256>>>(X);
    argmin_mma_kernel<<<N / 128, 256, SMEM_TOTAL>>>();
    gather_kernel<<<N, 64>>>(out, N);
}

// round 4
// speedup vs baseline: 4.8737x; 2.0353x over previous
#include <cuda_runtime.h>
#include <cuda_fp16.h>
#include <cstdint>

#define D_DIM 256
#define N_TOK 32768
#define N_CODE 2048

// ---------------- scratch (static device globals) ---------------------------
__device__ __half g_xhi[N_TOK * D_DIM];   // X hi split, m16n8k16 A-fragment order
__device__ __half g_xlo[N_TOK * D_DIM];   // X lo split
__device__ __half g_ehi[N_CODE * D_DIM];  // E hi split, B-fragment order
__device__ __half g_elo[N_CODE * D_DIM];  // E lo split
__device__ float  g_embed[N_CODE * D_DIM];// E row-major (gather)
__device__ float  g_esq[N_CODE];          // ||e||^2

// ---------------- helpers ----------------------------------------------------
__device__ __forceinline__ uint32_t smem_u32(const void* p) {
    uint32_t a;
    asm("{ .reg .u64 t; cvta.to.shared.u64 t, %1; cvt.u32.u64 %0, t; }"
        : "=r"(a) : "l"(p));
    return a;
}
__device__ __forceinline__ uint32_t pack2(__half a, __half b) {
    __half2 h2 = __halves2half2(a, b);
    return *reinterpret_cast<uint32_t*>(&h2);
}

#define MBAR_INIT(a, c) asm volatile("mbarrier.init.shared.b64 [%0], %1;" :: "r"(a), "r"((uint32_t)(c)) : "memory")
#define MBAR_EXPECT_TX(a, b) asm volatile("mbarrier.arrive.expect_tx.shared.b64 _, [%0], %1;" :: "r"(a), "r"((uint32_t)(b)) : "memory")
#define MBAR_ARRIVE(a)  asm volatile("mbarrier.arrive.shared.b64 _, [%0];" :: "r"(a) : "memory")

#define MBAR_WAIT(mbar, parity) do {                                          \
    uint32_t _m = (mbar), _ph = (parity), _done;                              \
    asm volatile("{ .reg .pred p; mbarrier.try_wait.parity.acquire.cta.shared::cta.b64 p, [%1], %2; selp.b32 %0, 1, 0, p; }" \
                 : "=r"(_done) : "r"(_m), "r"(_ph) : "memory");               \
    if (!_done) {                                                             \
        asm volatile("{ .reg .pred P1; WL_%=: mbarrier.try_wait.parity.acquire.cta.shared::cta.b64 P1, [%0], %1, 0x989680; @P1 bra.uni WD_%=; bra.uni WL_%=; WD_%=: }" \
                     :: "r"(_m), "r"(_ph) : "memory");                        \
    }                                                                         \
} while (0)

#define BULK_G2S(dst, src, bytes, mbar)                                       \
    asm volatile("cp.async.bulk.shared::cluster.global.mbarrier::complete_tx::bytes [%0], [%1], %2, [%3];" \
                 :: "r"(dst), "l"(src), "r"((uint32_t)(bytes)), "r"(mbar) : "memory")

// mma.sync m16n8k16 fp16 -> fp32 accumulate
__device__ __forceinline__ void mma_f16(float* d, const uint32_t* a, const uint32_t* b) {
    asm("mma.sync.aligned.m16n8k16.row.col.f32.f16.f16.f32 "
        "{%0,%1,%2,%3}, {%4,%5,%6,%7}, {%8,%9}, {%0,%1,%2,%3};"
        : "+f"(d[0]), "+f"(d[1]), "+f"(d[2]), "+f"(d[3])
        : "r"(a[0]), "r"(a[1]), "r"(a[2]), "r"(a[3]), "r"(b[0]), "r"(b[1]));
}

// ---------------------------------------------------------------------------
// prep_e: embed = embed_sum / max(u,eps); row-major copy, esq, fp16 split in
// B-fragment order (m16n8k16, col): per chunk (128 codes x 64 d):
//   half_idx = ((ks*16 + n_tile)*32 + lane)*4 + reg*2 + (kc&1)
//   lane = ncol*4 + ((kc>>1)&3), reg = kc>>3
// Block: 128 threads, each handles d = 2t, 2t+1 (pair -> one uint32).
// ---------------------------------------------------------------------------
__global__ void prep_e_kernel(const float* __restrict__ embed_sum,
                              const float* __restrict__ usage) {
    int k = blockIdx.x, t = threadIdx.x;
    float u = fmaxf(usage[k], 1e-5f);
    float2 vv = ((const float2*)embed_sum)[k * 128 + t];
    float v0 = vv.x / u, v1 = vv.y / u;
    ((float2*)g_embed)[k * 128 + t] = make_float2(v0, v1);

    __half h0 = __float2half_rn(v0);
    __half l0 = __float2half_rn(v0 - __half2float(h0));
    __half h1 = __float2half_rn(v1);
    __half l1 = __float2half_rn(v1 - __half2float(h1));

    int d = 2 * t;
    int pass = k >> 7, n_in = k & 127;
    int n_tile = n_in >> 3, ncol = n_in & 7;
    int ch = d >> 6, kk = d & 63, ks = kk >> 4, kc = kk & 15;
    int lane = ncol * 4 + ((kc >> 1) & 3);
    int reg = kc >> 3;
    int hbase = (pass * 4 + ch) * 8192 + ((ks * 16 + n_tile) * 32 + lane) * 4 + reg * 2;
    ((uint32_t*)g_ehi)[hbase >> 1] = pack2(h0, h1);
    ((uint32_t*)g_elo)[hbase >> 1] = pack2(l0, l1);

    __shared__ float red[128];
    red[t] = v0 * v0 + v1 * v1;
    __syncthreads();
    #pragma unroll
    for (int s = 64; s > 0; s >>= 1) {
        if (t < s) red[t] += red[t + s];
        __syncthreads();
    }
    if (t == 0) g_esq[k] = red[0];
}

// ---------------------------------------------------------------------------
// split_x: fp16 split of X in A-fragment order (m16n8k16, row):
//   half_idx = ((ks*8 + m_tile)*32 + lane)*8 + reg*2 + (kc&1)
//   lane = (r&7)*4 + ((kc>>1)&3), reg = (r>>3) | ((kc>>3)<<1)
// ---------------------------------------------------------------------------
__global__ void split_x_kernel(const float* __restrict__ X) {
    int i4 = blockIdx.x * blockDim.x + threadIdx.x;   // float4 index
    int n = i4 >> 6;
    int d0 = (i4 & 63) * 4;
    float4 x = ((const float4*)X)[i4];
    float xv[4] = {x.x, x.y, x.z, x.w};

    int m_block = n >> 7, m_in = n & 127;
    int m_tile = m_in >> 4, r = m_in & 15;

    #pragma unroll
    for (int j = 0; j < 4; j += 2) {
        int d = d0 + j;
        __half ha = __float2half_rn(xv[j]);
        __half la = __float2half_rn(xv[j] - __half2float(ha));
        __half hb = __float2half_rn(xv[j + 1]);
        __half lb = __float2half_rn(xv[j + 1] - __half2float(hb));

        int ch = d >> 6, kk = d & 63, ks = kk >> 4, kc = kk & 15;
        int lane = (r & 7) * 4 + ((kc >> 1) & 3);
        int reg = (r >> 3) | ((kc >> 3) << 1);
        int hbase = (m_block * 4 + ch) * 8192 + ((ks * 8 + m_tile) * 32 + lane) * 8 + reg * 2;
        ((uint32_t*)g_xhi)[hbase >> 1] = pack2(ha, hb);
        ((uint32_t*)g_xlo)[hbase >> 1] = pack2(la, lb);
    }
}

// ---------------------------------------------------------------------------
// Fused fp16x2 mma.sync GEMM + argmin + gather.
// 288 threads = 8 compute warps (4m x 2n) + 1 producer warp.
// CTA tile: 128 tokens x 128 codes/pass, 16 passes, K=256 in 4 chunks of 64,
// 3-stage cp.async.bulk pipeline (64 KB/stage).
// ---------------------------------------------------------------------------
#define SMEM_TOTAL (16384 + 3 * 65536)

__global__ void __launch_bounds__(288, 1) argmin_mma_kernel(float* __restrict__ out, int N) {
    extern __shared__ __align__(1024) char smem[];
    uint32_t sb = smem_u32(smem);
    int tid = threadIdx.x, lane = tid & 31, wid = tid >> 5;

    const uint32_t FB[3] = {sb + 0,  sb + 8,  sb + 16};
    const uint32_t EB[3] = {sb + 24, sb + 32, sb + 40};
    float* candD = (float*)(smem + 64);              // [2][128]
    int*   candI = (int*)(smem + 64 + 1024);         // [2][128]
    int*   finI  = (int*)(smem + 64 + 2048);         // [128]
    float* esq_s = (float*)(smem + 4096);            // [2048]

    if (tid == 0) {
        #pragma unroll
        for (int s = 0; s < 3; ++s) { MBAR_INIT(FB[s], 1); MBAR_INIT(EB[s], 8); }
    }
    for (int i = tid; i < N_CODE; i += 288) esq_s[i] = g_esq[i];
    __syncthreads();

    int row0 = blockIdx.x * 128;

    if (wid == 8) {
        // ---------------- dedicated producer warp ---------------------------
        if (lane == 0) {
            #pragma unroll 1
            for (int g = 0; g < 64; ++g) {
                int s = g % 3;
                if (g >= 3) MBAR_WAIT(EB[s], ((g / 3) + 1) & 1);
                int pass = g >> 2, ch = g & 3;
                uint32_t st = sb + 16384 + s * 65536;
                MBAR_EXPECT_TX(FB[s], 65536);
                BULK_G2S(st,         &g_xhi[(blockIdx.x * 4 + ch) * 8192], 16384, FB[s]);
                BULK_G2S(st + 16384, &g_xlo[(blockIdx.x * 4 + ch) * 8192], 16384, FB[s]);
                BULK_G2S(st + 32768, &g_ehi[(pass * 4 + ch) * 8192], 16384, FB[s]);
                BULK_G2S(st + 49152, &g_elo[(pass * 4 + ch) * 8192], 16384, FB[s]);
            }
        }
    } else {
        // ---------------- 8 compute warps ------------------------------------
        int warp_m = wid & 3, warp_n = wid >> 2;
        int t4 = lane & 3, g4 = lane >> 2;

        float best[2][2];
        int bestI[2][2];
        #pragma unroll
        for (int a = 0; a < 2; ++a)
            #pragma unroll
            for (int b = 0; b < 2; ++b) { best[a][b] = 3.4e38f; bestI[a][b] = 0; }

        #pragma unroll 1
        for (int pass = 0; pass < 16; ++pass) {
            float acc[2][8][4];
            #pragma unroll
            for (int mt = 0; mt < 2; ++mt)
                #pragma unroll
                for (int nt = 0; nt < 8; ++nt)
                    #pragma unroll
                    for (int j = 0; j < 4; ++j) acc[mt][nt][j] = 0.f;

            #pragma unroll 1
            for (int ch = 0; ch < 4; ++ch) {
                int g = pass * 4 + ch;
                int s = g % 3;
                MBAR_WAIT(FB[s], (g / 3) & 1);

                const char* stg = smem + 16384 + s * 65536;
                const char* Ah = stg;
                const char* Al = stg + 16384;
                const char* Bh = stg + 32768;
                const char* Bl = stg + 49152;

                #pragma unroll
                for (int ks = 0; ks < 4; ++ks) {
                    uint32_t ah[2][4], al[2][4];
                    #pragma unroll
                    for (int mt = 0; mt < 2; ++mt) {
                        int off = ((ks * 8 + warp_m * 2 + mt) * 32 + lane) * 16;
                        *(uint4*)ah[mt] = *(const uint4*)(Ah + off);
                        *(uint4*)al[mt] = *(const uint4*)(Al + off);
                    }
                    uint32_t bh[8][2], bl[8][2];
                    #pragma unroll
                    for (int nt = 0; nt < 8; ++nt) {
                        int off = ((ks * 16 + warp_n * 8 + nt) * 32 + lane) * 8;
                        *(uint2*)bh[nt] = *(const uint2*)(Bh + off);
                        *(uint2*)bl[nt] = *(const uint2*)(Bl + off);
                    }
                    // term-ordered: hi*hi, hi*lo, lo*hi
                    #pragma unroll
                    for (int mt = 0; mt < 2; ++mt)
                        #pragma unroll
                        for (int nt = 0; nt < 8; ++nt)
                            mma_f16(acc[mt][nt], ah[mt], bh[nt]);
                    #pragma unroll
                    for (int mt = 0; mt < 2; ++mt)
                        #pragma unroll
                        for (int nt = 0; nt < 8; ++nt)
                            mma_f16(acc[mt][nt], ah[mt], bl[nt]);
                    #pragma unroll
                    for (int mt = 0; mt < 2; ++mt)
                        #pragma unroll
                        for (int nt = 0; nt < 8; ++nt)
                            mma_f16(acc[mt][nt], al[mt], bh[nt]);
                }
                if (lane == 0) MBAR_ARRIVE(EB[s]);
            }

            // fold pass into running argmin: dist = esq - 2*dot
            #pragma unroll
            for (int nt = 0; nt < 8; ++nt) {
                int cbase = pass * 128 + warp_n * 64 + nt * 8 + 2 * t4;
                float e0 = esq_s[cbase], e1 = esq_s[cbase + 1];
                #pragma unroll
                for (int mt = 0; mt < 2; ++mt) {
                    float d0v = fmaf(-2.f, acc[mt][nt][0], e0);
                    if (d0v < best[mt][0]) { best[mt][0] = d0v; bestI[mt][0] = cbase; }
                    float d1v = fmaf(-2.f, acc[mt][nt][1], e1);
                    if (d1v < best[mt][0]) { best[mt][0] = d1v; bestI[mt][0] = cbase + 1; }
                    float d2v = fmaf(-2.f, acc[mt][nt][2], e0);
                    if (d2v < best[mt][1]) { best[mt][1] = d2v; bestI[mt][1] = cbase; }
                    float d3v = fmaf(-2.f, acc[mt][nt][3], e1);
                    if (d3v < best[mt][1]) { best[mt][1] = d3v; bestI[mt][1] = cbase + 1; }
                }
            }
        }

        // width-4 shuffle reduce (4 lanes share each row)
        #pragma unroll
        for (int mt = 0; mt < 2; ++mt)
            #pragma unroll
            for (int h = 0; h < 2; ++h) {
                float b = best[mt][h];
                int bi = bestI[mt][h];
                #pragma unroll
                for (int off = 2; off > 0; off >>= 1) {
                    float ob = __shfl_down_sync(0xffffffffu, b, off, 4);
                    int obi = __shfl_down_sync(0xffffffffu, bi, off, 4);
                    if (ob < b || (ob == b && obi < bi)) { b = ob; bi = obi; }
                }
                if (t4 == 0) {
                    int tok = warp_m * 32 + mt * 16 + g4 + 8 * h;
                    candD[warp_n * 128 + tok] = b;
                    candI[warp_n * 128 + tok] = bi;
                }
            }
    }

    __syncthreads();
    // merge the two warp_n halves, write index output
    if (tid < 128) {
        float b0 = candD[tid], b1 = candD[128 + tid];
        int i0 = candI[tid], i1 = candI[128 + tid];
        int sel = (b1 < b0 || (b1 == b0 && i1 < i0)) ? i1 : i0;
        finI[tid] = sel;
        out[(size_t)N * D_DIM + row0 + tid] = (float)sel;
    }
    __syncthreads();

    // fused gather: 128 rows x 64 float4 (embed rows are L2-resident)
    #pragma unroll 1
    for (int i = tid; i < 128 * 64; i += 288) {
        int row = i >> 6, c4 = i & 63;
        int idx = finI[row];
        float4 v = ((const float4*)g_embed)[(size_t)idx * 64 + c4];
        ((float4*)out)[(size_t)(row0 + row) * 64 + c4] = v;
    }
}

// ---------------------------------------------------------------------------
extern "C" void kernel_launch(void* const* d_in, const int* in_sizes, int n_in,
                              void* d_out, int out_size) {
    const float* X  = (const float*)d_in[0];
    const float* ES = (const float*)d_in[1];
    const float* U  = (const float*)d_in[2];
    float* out = (float*)d_out;
    (void)n_in; (void)out_size;
    int N = in_sizes[0] / D_DIM;   // 32768

    cudaFuncSetAttribute(argmin_mma_kernel,
                         cudaFuncAttributeMaxDynamicSharedMemorySize, SMEM_TOTAL);

    prep_e_kernel<<<N_CODE, 128>>>(ES, U);
    split_x_kernel<<<(N * D_DIM / 4) / 256, 256>>>(X);
    argmin_mma_kernel<<<N / 128, 288, SMEM_TOTAL>>>(out, N);
}

// round 5
// speedup vs baseline: 5.3478x; 1.0973x over previous
#include <cuda_runtime.h>
#include <cuda_fp16.h>
#include <cstdint>

#define D_DIM 256
#define N_TOK 32768
#define N_CODE 2048

// ---------------- scratch (static device globals) ---------------------------
__device__ __half g_xhi[N_TOK * D_DIM];   // X hi split, m16n8k16 A-fragment order
__device__ __half g_xlo[N_TOK * D_DIM];   // X lo split
__device__ __half g_ehi[N_CODE * D_DIM];  // E hi split, B-fragment order
__device__ __half g_elo[N_CODE * D_DIM];  // E lo split
__device__ float  g_embed[N_CODE * D_DIM];// E row-major (gather)
__device__ float  g_esq[N_CODE];          // ||e||^2
__device__ unsigned long long g_key[N_TOK]; // packed (mono(dist)<<32 | code)

// ---------------- helpers ----------------------------------------------------
__device__ __forceinline__ uint32_t smem_u32(const void* p) {
    uint32_t a;
    asm("{ .reg .u64 t; cvta.to.shared.u64 t, %1; cvt.u32.u64 %0, t; }"
        : "=r"(a) : "l"(p));
    return a;
}
__device__ __forceinline__ uint32_t pack2(__half a, __half b) {
    __half2 h2 = __halves2half2(a, b);
    return *reinterpret_cast<uint32_t*>(&h2);
}
// monotone float->uint mapping (preserves total order)
__device__ __forceinline__ uint32_t fmono(float f) {
    uint32_t b = __float_as_uint(f);
    return b ^ ((b & 0x80000000u) ? 0xFFFFFFFFu : 0x80000000u);
}

#define MBAR_INIT(a, c) asm volatile("mbarrier.init.shared.b64 [%0], %1;" :: "r"(a), "r"((uint32_t)(c)) : "memory")
#define MBAR_EXPECT_TX(a, b) asm volatile("mbarrier.arrive.expect_tx.shared.b64 _, [%0], %1;" :: "r"(a), "r"((uint32_t)(b)) : "memory")
#define MBAR_ARRIVE(a)  asm volatile("mbarrier.arrive.shared.b64 _, [%0];" :: "r"(a) : "memory")

#define MBAR_WAIT(mbar, parity) do {                                          \
    uint32_t _m = (mbar), _ph = (parity), _done;                              \
    asm volatile("{ .reg .pred p; mbarrier.try_wait.parity.acquire.cta.shared::cta.b64 p, [%1], %2; selp.b32 %0, 1, 0, p; }" \
                 : "=r"(_done) : "r"(_m), "r"(_ph) : "memory");               \
    if (!_done) {                                                             \
        asm volatile("{ .reg .pred P1; WL_%=: mbarrier.try_wait.parity.acquire.cta.shared::cta.b64 P1, [%0], %1, 0x989680; @P1 bra.uni WD_%=; bra.uni WL_%=; WD_%=: }" \
                     :: "r"(_m), "r"(_ph) : "memory");                        \
    }                                                                         \
} while (0)

#define BULK_G2S(dst, src, bytes, mbar)                                       \
    asm volatile("cp.async.bulk.shared::cluster.global.mbarrier::complete_tx::bytes [%0], [%1], %2, [%3];" \
                 :: "r"(dst), "l"(src), "r"((uint32_t)(bytes)), "r"(mbar) : "memory")

// mma.sync m16n8k16 fp16 -> fp32 accumulate
__device__ __forceinline__ void mma_f16(float* d, const uint32_t* a, const uint32_t* b) {
    asm("mma.sync.aligned.m16n8k16.row.col.f32.f16.f16.f32 "
        "{%0,%1,%2,%3}, {%4,%5,%6,%7}, {%8,%9}, {%0,%1,%2,%3};"
        : "+f"(d[0]), "+f"(d[1]), "+f"(d[2]), "+f"(d[3])
        : "r"(a[0]), "r"(a[1]), "r"(a[2]), "r"(a[3]), "r"(b[0]), "r"(b[1]));
}

// ---------------------------------------------------------------------------
// prep_e: embed = embed_sum / max(u,eps); row-major copy, esq, fp16 split in
// B-fragment order (m16n8k16 col). Block: 128 threads, d pair per thread.
// ---------------------------------------------------------------------------
__global__ void prep_e_kernel(const float* __restrict__ embed_sum,
                              const float* __restrict__ usage) {
    int k = blockIdx.x, t = threadIdx.x;
    float u = fmaxf(usage[k], 1e-5f);
    float2 vv = ((const float2*)embed_sum)[k * 128 + t];
    float v0 = vv.x / u, v1 = vv.y / u;
    ((float2*)g_embed)[k * 128 + t] = make_float2(v0, v1);

    __half h0 = __float2half_rn(v0);
    __half l0 = __float2half_rn(v0 - __half2float(h0));
    __half h1 = __float2half_rn(v1);
    __half l1 = __float2half_rn(v1 - __half2float(h1));

    int d = 2 * t;
    int pass = k >> 7, n_in = k & 127;
    int n_tile = n_in >> 3, ncol = n_in & 7;
    int ch = d >> 6, kk = d & 63, ks = kk >> 4, kc = kk & 15;
    int lane = ncol * 4 + ((kc >> 1) & 3);
    int reg = kc >> 3;
    int hbase = (pass * 4 + ch) * 8192 + ((ks * 16 + n_tile) * 32 + lane) * 4 + reg * 2;
    ((uint32_t*)g_ehi)[hbase >> 1] = pack2(h0, h1);
    ((uint32_t*)g_elo)[hbase >> 1] = pack2(l0, l1);

    __shared__ float red[128];
    red[t] = v0 * v0 + v1 * v1;
    __syncthreads();
    #pragma unroll
    for (int s = 64; s > 0; s >>= 1) {
        if (t < s) red[t] += red[t + s];
        __syncthreads();
    }
    if (t == 0) g_esq[k] = red[0];
}

// ---------------------------------------------------------------------------
// split_x: fp16 split of X in A-fragment order + g_key init.
// ---------------------------------------------------------------------------
__global__ void split_x_kernel(const float* __restrict__ X) {
    int i4 = blockIdx.x * blockDim.x + threadIdx.x;   // float4 index
    if (i4 < N_TOK) g_key[i4] = 0xFFFFFFFFFFFFFFFFull;

    int n = i4 >> 6;
    int d0 = (i4 & 63) * 4;
    float4 x = ((const float4*)X)[i4];
    float xv[4] = {x.x, x.y, x.z, x.w};

    int m_block = n >> 7, m_in = n & 127;
    int m_tile = m_in >> 4, r = m_in & 15;

    #pragma unroll
    for (int j = 0; j < 4; j += 2) {
        int d = d0 + j;
        __half ha = __float2half_rn(xv[j]);
        __half la = __float2half_rn(xv[j] - __half2float(ha));
        __half hb = __float2half_rn(xv[j + 1]);
        __half lb = __float2half_rn(xv[j + 1] - __half2float(hb));

        int ch = d >> 6, kk = d & 63, ks = kk >> 4, kc = kk & 15;
        int lane = (r & 7) * 4 + ((kc >> 1) & 3);
        int reg = (r >> 3) | ((kc >> 3) << 1);
        int hbase = (m_block * 4 + ch) * 8192 + ((ks * 8 + m_tile) * 32 + lane) * 8 + reg * 2;
        ((uint32_t*)g_xhi)[hbase >> 1] = pack2(ha, hb);
        ((uint32_t*)g_xlo)[hbase >> 1] = pack2(la, lb);
    }
}

// ---------------------------------------------------------------------------
// Fused fp16x2 mma.sync GEMM + argmin over an (m-tile 128, n-quarter 512) unit.
// Grid: 1024 CTAs = 256 m-tiles x 4 quarters (mtile = bx>>2, q = bx&3).
// 288 threads = 8 compute warps (4m x 2n) + 1 producer warp.
// 4 passes x 128 codes, K=256 in 4 chunks of 64, 3-stage pipeline.
// Cross-CTA merge: atomicMin on packed u64 keys.
// ---------------------------------------------------------------------------
#define SMEM_TOTAL (16384 + 3 * 65536)

__global__ void __launch_bounds__(288, 1) argmin_mma_kernel() {
    extern __shared__ __align__(1024) char smem[];
    uint32_t sb = smem_u32(smem);
    int tid = threadIdx.x, lane = tid & 31, wid = tid >> 5;
    int mtile = blockIdx.x >> 2, q = blockIdx.x & 3;

    const uint32_t FB[3] = {sb + 0,  sb + 8,  sb + 16};
    const uint32_t EB[3] = {sb + 24, sb + 32, sb + 40};
    float* esq_s = (float*)(smem + 1024);   // [512] quarter esq

    if (tid == 0) {
        #pragma unroll
        for (int s = 0; s < 3; ++s) { MBAR_INIT(FB[s], 1); MBAR_INIT(EB[s], 8); }
    }
    for (int i = tid; i < 512; i += 288) esq_s[i] = g_esq[q * 512 + i];
    __syncthreads();

    int row0 = mtile * 128;

    if (wid == 8) {
        // ---------------- dedicated producer warp ---------------------------
        if (lane == 0) {
            #pragma unroll 1
            for (int g = 0; g < 16; ++g) {
                int s = g % 3;
                if (g >= 3) MBAR_WAIT(EB[s], ((g / 3) + 1) & 1);
                int pass = g >> 2, ch = g & 3;
                uint32_t st = sb + 16384 + s * 65536;
                MBAR_EXPECT_TX(FB[s], 65536);
                BULK_G2S(st,         &g_xhi[(mtile * 4 + ch) * 8192], 16384, FB[s]);
                BULK_G2S(st + 16384, &g_xlo[(mtile * 4 + ch) * 8192], 16384, FB[s]);
                BULK_G2S(st + 32768, &g_ehi[((q * 4 + pass) * 4 + ch) * 8192], 16384, FB[s]);
                BULK_G2S(st + 49152, &g_elo[((q * 4 + pass) * 4 + ch) * 8192], 16384, FB[s]);
            }
        }
    } else {
        // ---------------- 8 compute warps ------------------------------------
        int warp_m = wid & 3, warp_n = wid >> 2;
        int t4 = lane & 3, g4 = lane >> 2;

        float best[2][2];
        int bestI[2][2];
        #pragma unroll
        for (int a = 0; a < 2; ++a)
            #pragma unroll
            for (int b = 0; b < 2; ++b) { best[a][b] = 3.4e38f; bestI[a][b] = 0; }

        #pragma unroll 1
        for (int pass = 0; pass < 4; ++pass) {
            float acc[2][8][4];
            #pragma unroll
            for (int mt = 0; mt < 2; ++mt)
                #pragma unroll
                for (int nt = 0; nt < 8; ++nt)
                    #pragma unroll
                    for (int j = 0; j < 4; ++j) acc[mt][nt][j] = 0.f;

            #pragma unroll 1
            for (int ch = 0; ch < 4; ++ch) {
                int g = pass * 4 + ch;
                int s = g % 3;
                MBAR_WAIT(FB[s], (g / 3) & 1);

                const char* stg = smem + 16384 + s * 65536;
                const char* Ah = stg;
                const char* Al = stg + 16384;
                const char* Bh = stg + 32768;
                const char* Bl = stg + 49152;

                #pragma unroll
                for (int ks = 0; ks < 4; ++ks) {
                    uint32_t ah[2][4], al[2][4];
                    #pragma unroll
                    for (int mt = 0; mt < 2; ++mt) {
                        int off = ((ks * 8 + warp_m * 2 + mt) * 32 + lane) * 16;
                        *(uint4*)ah[mt] = *(const uint4*)(Ah + off);
                        *(uint4*)al[mt] = *(const uint4*)(Al + off);
                    }
                    uint32_t bh[8][2], bl[8][2];
                    #pragma unroll
                    for (int nt = 0; nt < 8; ++nt) {
                        int off = ((ks * 16 + warp_n * 8 + nt) * 32 + lane) * 8;
                        *(uint2*)bh[nt] = *(const uint2*)(Bh + off);
                        *(uint2*)bl[nt] = *(const uint2*)(Bl + off);
                    }
                    // term-ordered: hi*hi, hi*lo, lo*hi
                    #pragma unroll
                    for (int mt = 0; mt < 2; ++mt)
                        #pragma unroll
                        for (int nt = 0; nt < 8; ++nt)
                            mma_f16(acc[mt][nt], ah[mt], bh[nt]);
                    #pragma unroll
                    for (int mt = 0; mt < 2; ++mt)
                        #pragma unroll
                        for (int nt = 0; nt < 8; ++nt)
                            mma_f16(acc[mt][nt], ah[mt], bl[nt]);
                    #pragma unroll
                    for (int mt = 0; mt < 2; ++mt)
                        #pragma unroll
                        for (int nt = 0; nt < 8; ++nt)
                            mma_f16(acc[mt][nt], al[mt], bh[nt]);
                }
                if (lane == 0) MBAR_ARRIVE(EB[s]);
            }

            // fold pass into running argmin: dist = esq - 2*dot
            #pragma unroll
            for (int nt = 0; nt < 8; ++nt) {
                int clocal = pass * 128 + warp_n * 64 + nt * 8 + 2 * t4;
                float e0 = esq_s[clocal], e1 = esq_s[clocal + 1];
                int cbase = q * 512 + clocal;
                #pragma unroll
                for (int mt = 0; mt < 2; ++mt) {
                    float d0v = fmaf(-2.f, acc[mt][nt][0], e0);
                    if (d0v < best[mt][0]) { best[mt][0] = d0v; bestI[mt][0] = cbase; }
                    float d1v = fmaf(-2.f, acc[mt][nt][1], e1);
                    if (d1v < best[mt][0]) { best[mt][0] = d1v; bestI[mt][0] = cbase + 1; }
                    float d2v = fmaf(-2.f, acc[mt][nt][2], e0);
                    if (d2v < best[mt][1]) { best[mt][1] = d2v; bestI[mt][1] = cbase; }
                    float d3v = fmaf(-2.f, acc[mt][nt][3], e1);
                    if (d3v < best[mt][1]) { best[mt][1] = d3v; bestI[mt][1] = cbase + 1; }
                }
            }
        }

        // width-4 shuffle reduce, then global atomic merge
        #pragma unroll
        for (int mt = 0; mt < 2; ++mt)
            #pragma unroll
            for (int h = 0; h < 2; ++h) {
                float b = best[mt][h];
                int bi = bestI[mt][h];
                #pragma unroll
                for (int off = 2; off > 0; off >>= 1) {
                    float ob = __shfl_down_sync(0xffffffffu, b, off, 4);
                    int obi = __shfl_down_sync(0xffffffffu, bi, off, 4);
                    if (ob < b || (ob == b && obi < bi)) { b = ob; bi = obi; }
                }
                if (t4 == 0) {
                    int tok = row0 + warp_m * 32 + mt * 16 + g4 + 8 * h;
                    unsigned long long key =
                        ((unsigned long long)fmono(b) << 32) | (uint32_t)bi;
                    atomicMin(&g_key[tok], key);
                }
            }
    }
}

// ---------------------------------------------------------------------------
// gather: quantize[n] = embed[idx[n]]; indices (as float) appended after.
// 256 blocks x 256 threads; block handles 128 tokens, 4 tokens per iteration.
// ---------------------------------------------------------------------------
__global__ void __launch_bounds__(256) gather_kernel(float* __restrict__ out, int N) {
    int bx = blockIdx.x, tid = threadIdx.x;
    int tloc = tid >> 6, c4 = tid & 63;
    #pragma unroll 1
    for (int it = 0; it < 32; ++it) {
        int tok = bx * 128 + it * 4 + tloc;
        int idx = (int)(g_key[tok] & 0xFFFFFFFFull);
        float4 v = ((const float4*)g_embed)[(size_t)idx * 64 + c4];
        ((float4*)out)[(size_t)tok * 64 + c4] = v;
    }
    if (tid < 128) {
        int tok = bx * 128 + tid;
        int idx = (int)(g_key[tok] & 0xFFFFFFFFull);
        out[(size_t)N * D_DIM + tok] = (float)idx;
    }
}

// ---------------------------------------------------------------------------
extern "C" void kernel_launch(void* const* d_in, const int* in_sizes, int n_in,
                              void* d_out, int out_size) {
    const float* X  = (const float*)d_in[0];
    const float* ES = (const float*)d_in[1];
    const float* U  = (const float*)d_in[2];
    float* out = (float*)d_out;
    (void)n_in; (void)out_size;
    int N = in_sizes[0] / D_DIM;   // 32768

    cudaFuncSetAttribute(argmin_mma_kernel,
                         cudaFuncAttributeMaxDynamicSharedMemorySize, SMEM_TOTAL);

    prep_e_kernel<<<N_CODE, 128>>>(ES, U);
    split_x_kernel<<<(N * D_DIM / 4) / 256, 256>>>(X);
    argmin_mma_kernel<<<(N / 128) * 4, 288, SMEM_TOTAL>>>();
    gather_kernel<<<N / 128, 256>>>(out, N);
}

// round 6
// speedup vs baseline: 5.4896x; 1.0265x over previous
#include <cuda_runtime.h>
#include <cuda_fp16.h>
#include <cstdint>

#define D_DIM 256
#define N_TOK 32768
#define N_CODE 2048

// ---------------- scratch (static device globals) ---------------------------
__device__ __half g_xhi[N_TOK * D_DIM];   // X hi split, m16n8k16 A-fragment order
__device__ __half g_xlo[N_TOK * D_DIM];   // X lo split
__device__ __half g_ehi[N_CODE * D_DIM];  // E hi split, B-fragment order
__device__ __half g_elo[N_CODE * D_DIM];  // E lo split
__device__ float  g_embed[N_CODE * D_DIM];// E row-major (gather)
__device__ float  g_esq[N_CODE];          // ||e||^2
__device__ unsigned long long g_key[N_TOK]; // packed (mono(dist)<<32 | code)

// ---------------- helpers ----------------------------------------------------
__device__ __forceinline__ uint32_t smem_u32(const void* p) {
    uint32_t a;
    asm("{ .reg .u64 t; cvta.to.shared.u64 t, %1; cvt.u32.u64 %0, t; }"
        : "=r"(a) : "l"(p));
    return a;
}
__device__ __forceinline__ uint32_t pack2(__half a, __half b) {
    __half2 h2 = __halves2half2(a, b);
    return *reinterpret_cast<uint32_t*>(&h2);
}
// monotone float->uint mapping (preserves total order)
__device__ __forceinline__ uint32_t fmono(float f) {
    uint32_t b = __float_as_uint(f);
    return b ^ ((b & 0x80000000u) ? 0xFFFFFFFFu : 0x80000000u);
}

#define MBAR_INIT(a, c) asm volatile("mbarrier.init.shared.b64 [%0], %1;" :: "r"(a), "r"((uint32_t)(c)) : "memory")
#define MBAR_EXPECT_TX(a, b) asm volatile("mbarrier.arrive.expect_tx.shared.b64 _, [%0], %1;" :: "r"(a), "r"((uint32_t)(b)) : "memory")
#define MBAR_ARRIVE(a)  asm volatile("mbarrier.arrive.shared.b64 _, [%0];" :: "r"(a) : "memory")

#define MBAR_WAIT(mbar, parity) do {                                          \
    uint32_t _m = (mbar), _ph = (parity), _done;                              \
    asm volatile("{ .reg .pred p; mbarrier.try_wait.parity.acquire.cta.shared::cta.b64 p, [%1], %2; selp.b32 %0, 1, 0, p; }" \
                 : "=r"(_done) : "r"(_m), "r"(_ph) : "memory");               \
    if (!_done) {                                                             \
        asm volatile("{ .reg .pred P1; WL_%=: mbarrier.try_wait.parity.acquire.cta.shared::cta.b64 P1, [%0], %1, 0x989680; @P1 bra.uni WD_%=; bra.uni WL_%=; WD_%=: }" \
                     :: "r"(_m), "r"(_ph) : "memory");                        \
    }                                                                         \
} while (0)

#define BULK_G2S(dst, src, bytes, mbar)                                       \
    asm volatile("cp.async.bulk.shared::cluster.global.mbarrier::complete_tx::bytes [%0], [%1], %2, [%3];" \
                 :: "r"(dst), "l"(src), "r"((uint32_t)(bytes)), "r"(mbar) : "memory")

// mma.sync m16n8k16 fp16 -> fp32 accumulate
__device__ __forceinline__ void mma_f16(float* d, const uint32_t* a, const uint32_t* b) {
    asm("mma.sync.aligned.m16n8k16.row.col.f32.f16.f16.f32 "
        "{%0,%1,%2,%3}, {%4,%5,%6,%7}, {%8,%9}, {%0,%1,%2,%3};"
        : "+f"(d[0]), "+f"(d[1]), "+f"(d[2]), "+f"(d[3])
        : "r"(a[0]), "r"(a[1]), "r"(a[2]), "r"(a[3]), "r"(b[0]), "r"(b[1]));
}

// ---------------------------------------------------------------------------
// Fused prep: blocks [0, 2048) do E prep (128 active threads, one code each);
// blocks [2048, 2048+8192) do X split (one float4 per thread) + g_key init.
// ---------------------------------------------------------------------------
__global__ void __launch_bounds__(256) prep_all_kernel(const float* __restrict__ X,
                                                       const float* __restrict__ embed_sum,
                                                       const float* __restrict__ usage) {
    if (blockIdx.x < N_CODE) {
        // -------- E prep: embed, esq, fp16 split in B-fragment order --------
        int k = blockIdx.x, t = threadIdx.x;
        __shared__ float red[128];
        if (t < 128) {
            float u = fmaxf(usage[k], 1e-5f);
            float2 vv = ((const float2*)embed_sum)[k * 128 + t];
            float v0 = vv.x / u, v1 = vv.y / u;
            ((float2*)g_embed)[k * 128 + t] = make_float2(v0, v1);

            __half h0 = __float2half_rn(v0);
            __half l0 = __float2half_rn(v0 - __half2float(h0));
            __half h1 = __float2half_rn(v1);
            __half l1 = __float2half_rn(v1 - __half2float(h1));

            int d = 2 * t;
            int pass = k >> 7, n_in = k & 127;
            int n_tile = n_in >> 3, ncol = n_in & 7;
            int ch = d >> 6, kk = d & 63, ks = kk >> 4, kc = kk & 15;
            int lane = ncol * 4 + ((kc >> 1) & 3);
            int reg = kc >> 3;
            int hbase = (pass * 4 + ch) * 8192 + ((ks * 16 + n_tile) * 32 + lane) * 4 + reg * 2;
            ((uint32_t*)g_ehi)[hbase >> 1] = pack2(h0, h1);
            ((uint32_t*)g_elo)[hbase >> 1] = pack2(l0, l1);

            red[t] = v0 * v0 + v1 * v1;
        }
        __syncthreads();
        if (t < 128) {
            #pragma unroll
            for (int s = 64; s > 0; s >>= 1) {
                if (t < s) red[t] += red[t + s];
                __syncwarp(0xffffffffu);
                if (s > 32) __syncthreads();
            }
            if (t == 0) g_esq[k] = red[0];
        }
    } else {
        // -------- X split: fp16 split in A-fragment order + key init --------
        int i4 = (blockIdx.x - N_CODE) * 256 + threadIdx.x;   // float4 index
        if (i4 < N_TOK) g_key[i4] = 0xFFFFFFFFFFFFFFFFull;

        int n = i4 >> 6;
        int d0 = (i4 & 63) * 4;
        float4 x = ((const float4*)X)[i4];
        float xv[4] = {x.x, x.y, x.z, x.w};

        int m_block = n >> 7, m_in = n & 127;
        int m_tile = m_in >> 4, r = m_in & 15;

        #pragma unroll
        for (int j = 0; j < 4; j += 2) {
            int d = d0 + j;
            __half ha = __float2half_rn(xv[j]);
            __half la = __float2half_rn(xv[j] - __half2float(ha));
            __half hb = __float2half_rn(xv[j + 1]);
            __half lb = __float2half_rn(xv[j + 1] - __half2float(hb));

            int ch = d >> 6, kk = d & 63, ks = kk >> 4, kc = kk & 15;
            int lane = (r & 7) * 4 + ((kc >> 1) & 3);
            int reg = (r >> 3) | ((kc >> 3) << 1);
            int hbase = (m_block * 4 + ch) * 8192 + ((ks * 8 + m_tile) * 32 + lane) * 8 + reg * 2;
            ((uint32_t*)g_xhi)[hbase >> 1] = pack2(ha, hb);
            ((uint32_t*)g_xlo)[hbase >> 1] = pack2(la, lb);
        }
    }
}

// ---------------------------------------------------------------------------
// Fused fp16x2 mma.sync GEMM + argmin over an (m-tile 128, n-quarter 512) unit.
// Grid: 1024 CTAs = 256 m-tiles x 4 quarters (mtile = bx>>2, q = bx&3).
// 288 threads = 8 compute warps (4m x 2n) + 1 producer warp.
// 4 passes x 128 codes, K=256 in 4 chunks of 64, 3-stage pipeline.
// Cross-CTA merge: atomicMin on packed u64 keys.
// ---------------------------------------------------------------------------
#define SMEM_TOTAL (16384 + 3 * 65536)

__global__ void __launch_bounds__(288, 1) argmin_mma_kernel() {
    extern __shared__ __align__(1024) char smem[];
    uint32_t sb = smem_u32(smem);
    int tid = threadIdx.x, lane = tid & 31, wid = tid >> 5;
    int mtile = blockIdx.x >> 2, q = blockIdx.x & 3;

    const uint32_t FB[3] = {sb + 0,  sb + 8,  sb + 16};
    const uint32_t EB[3] = {sb + 24, sb + 32, sb + 40};
    float* esq_s = (float*)(smem + 1024);   // [512] quarter esq

    if (tid == 0) {
        #pragma unroll
        for (int s = 0; s < 3; ++s) { MBAR_INIT(FB[s], 1); MBAR_INIT(EB[s], 8); }
    }
    for (int i = tid; i < 512; i += 288) esq_s[i] = g_esq[q * 512 + i];
    __syncthreads();

    int row0 = mtile * 128;

    if (wid == 8) {
        // ---------------- dedicated producer warp ---------------------------
        if (lane == 0) {
            #pragma unroll 1
            for (int g = 0; g < 16; ++g) {
                int s = g % 3;
                if (g >= 3) MBAR_WAIT(EB[s], ((g / 3) + 1) & 1);
                int pass = g >> 2, ch = g & 3;
                uint32_t st = sb + 16384 + s * 65536;
                MBAR_EXPECT_TX(FB[s], 65536);
                BULK_G2S(st,         &g_xhi[(mtile * 4 + ch) * 8192], 16384, FB[s]);
                BULK_G2S(st + 16384, &g_xlo[(mtile * 4 + ch) * 8192], 16384, FB[s]);
                BULK_G2S(st + 32768, &g_ehi[((q * 4 + pass) * 4 + ch) * 8192], 16384, FB[s]);
                BULK_G2S(st + 49152, &g_elo[((q * 4 + pass) * 4 + ch) * 8192], 16384, FB[s]);
            }
        }
    } else {
        // ---------------- 8 compute warps ------------------------------------
        int warp_m = wid & 3, warp_n = wid >> 2;
        int t4 = lane & 3, g4 = lane >> 2;

        float best[2][2];
        int bestI[2][2];
        #pragma unroll
        for (int a = 0; a < 2; ++a)
            #pragma unroll
            for (int b = 0; b < 2; ++b) { best[a][b] = 3.4e38f; bestI[a][b] = 0; }

        #pragma unroll 1
        for (int pass = 0; pass < 4; ++pass) {
            float acc[2][8][4];
            #pragma unroll
            for (int mt = 0; mt < 2; ++mt)
                #pragma unroll
                for (int nt = 0; nt < 8; ++nt)
                    #pragma unroll
                    for (int j = 0; j < 4; ++j) acc[mt][nt][j] = 0.f;

            #pragma unroll 1
            for (int ch = 0; ch < 4; ++ch) {
                int g = pass * 4 + ch;
                int s = g % 3;
                MBAR_WAIT(FB[s], (g / 3) & 1);

                const char* stg = smem + 16384 + s * 65536;
                const char* Ah = stg;
                const char* Al = stg + 16384;
                const char* Bh = stg + 32768;
                const char* Bl = stg + 49152;

                #pragma unroll
                for (int ks = 0; ks < 4; ++ks) {
                    uint32_t ah[2][4], al[2][4];
                    #pragma unroll
                    for (int mt = 0; mt < 2; ++mt) {
                        int off = ((ks * 8 + warp_m * 2 + mt) * 32 + lane) * 16;
                        *(uint4*)ah[mt] = *(const uint4*)(Ah + off);
                        *(uint4*)al[mt] = *(const uint4*)(Al + off);
                    }
                    uint32_t bh[8][2], bl[8][2];
                    #pragma unroll
                    for (int nt = 0; nt < 8; ++nt) {
                        int off = ((ks * 16 + warp_n * 8 + nt) * 32 + lane) * 8;
                        *(uint2*)bh[nt] = *(const uint2*)(Bh + off);
                        *(uint2*)bl[nt] = *(const uint2*)(Bl + off);
                    }
                    // term-ordered: hi*hi, hi*lo, lo*hi
                    #pragma unroll
                    for (int mt = 0; mt < 2; ++mt)
                        #pragma unroll
                        for (int nt = 0; nt < 8; ++nt)
                            mma_f16(acc[mt][nt], ah[mt], bh[nt]);
                    #pragma unroll
                    for (int mt = 0; mt < 2; ++mt)
                        #pragma unroll
                        for (int nt = 0; nt < 8; ++nt)
                            mma_f16(acc[mt][nt], ah[mt], bl[nt]);
                    #pragma unroll
                    for (int mt = 0; mt < 2; ++mt)
                        #pragma unroll
                        for (int nt = 0; nt < 8; ++nt)
                            mma_f16(acc[mt][nt], al[mt], bh[nt]);
                }
                if (lane == 0) MBAR_ARRIVE(EB[s]);
            }

            // fold pass into running argmin: dist = esq - 2*dot
            #pragma unroll
            for (int nt = 0; nt < 8; ++nt) {
                int clocal = pass * 128 + warp_n * 64 + nt * 8 + 2 * t4;
                float e0 = esq_s[clocal], e1 = esq_s[clocal + 1];
                int cbase = q * 512 + clocal;
                #pragma unroll
                for (int mt = 0; mt < 2; ++mt) {
                    float d0v = fmaf(-2.f, acc[mt][nt][0], e0);
                    if (d0v < best[mt][0]) { best[mt][0] = d0v; bestI[mt][0] = cbase; }
                    float d1v = fmaf(-2.f, acc[mt][nt][1], e1);
                    if (d1v < best[mt][0]) { best[mt][0] = d1v; bestI[mt][0] = cbase + 1; }
                    float d2v = fmaf(-2.f, acc[mt][nt][2], e0);
                    if (d2v < best[mt][1]) { best[mt][1] = d2v; bestI[mt][1] = cbase; }
                    float d3v = fmaf(-2.f, acc[mt][nt][3], e1);
                    if (d3v < best[mt][1]) { best[mt][1] = d3v; bestI[mt][1] = cbase + 1; }
                }
            }
        }

        // width-4 shuffle reduce, then global atomic merge
        #pragma unroll
        for (int mt = 0; mt < 2; ++mt)
            #pragma unroll
            for (int h = 0; h < 2; ++h) {
                float b = best[mt][h];
                int bi = bestI[mt][h];
                #pragma unroll
                for (int off = 2; off > 0; off >>= 1) {
                    float ob = __shfl_down_sync(0xffffffffu, b, off, 4);
                    int obi = __shfl_down_sync(0xffffffffu, bi, off, 4);
                    if (ob < b || (ob == b && obi < bi)) { b = ob; bi = obi; }
                }
                if (t4 == 0) {
                    int tok = row0 + warp_m * 32 + mt * 16 + g4 + 8 * h;
                    unsigned long long key =
                        ((unsigned long long)fmono(b) << 32) | (uint32_t)bi;
                    atomicMin(&g_key[tok], key);
                }
            }
    }
}

// ---------------------------------------------------------------------------
// gather: one thread per (token, float4 chunk). 8192 CTAs x 256 threads.
// 16 consecutive threads share a token -> key load broadcasts; embed reads
// and out writes fully coalesced. Index (as float) written by c4==0 lane.
// ---------------------------------------------------------------------------
__global__ void __launch_bounds__(256) gather_kernel(float* __restrict__ out, int N) {
    int i = blockIdx.x * 256 + threadIdx.x;     // [0, N*64)
    int tok = i >> 6, c4 = i & 63;
    int idx = (int)(g_key[tok] & 0xFFFFFFFFull);
    float4 v = ((const float4*)g_embed)[(size_t)idx * 64 + c4];
    ((float4*)out)[i] = v;
    if (c4 == 0) out[(size_t)N * D_DIM + tok] = (float)idx;
}

// ---------------------------------------------------------------------------
extern "C" void kernel_launch(void* const* d_in, const int* in_sizes, int n_in,
                              void* d_out, int out_size) {
    const float* X  = (const float*)d_in[0];
    const float* ES = (const float*)d_in[1];
    const float* U  = (const float*)d_in[2];
    float* out = (float*)d_out;
    (void)n_in; (void)out_size;
    int N = in_sizes[0] / D_DIM;   // 32768

    cudaFuncSetAttribute(argmin_mma_kernel,
                         cudaFuncAttributeMaxDynamicSharedMemorySize, SMEM_TOTAL);

    prep_all_kernel<<<N_CODE + (N * 64) / 256, 256>>>(X, ES, U);
    argmin_mma_kernel<<<(N / 128) * 4, 288, SMEM_TOTAL>>>();
    gather_kernel<<<(N * 64) / 256, 256>>>(out, N);
}

// round 7
// speedup vs baseline: 5.5744x; 1.0154x over previous
#include <cuda_runtime.h>
#include <cuda_fp16.h>
#include <cstdint>

#define D_DIM 256
#define N_TOK 32768
#define N_CODE 2048

// ---------------- scratch (static device globals) ---------------------------
__device__ __half g_xhi[N_TOK * D_DIM];   // X hi split, m16n8k16 A-fragment order
__device__ __half g_xlo[N_TOK * D_DIM];   // X lo split
__device__ __half g_ehi[N_CODE * D_DIM];  // E hi split, B-fragment order
__device__ __half g_elo[N_CODE * D_DIM];  // E lo split
__device__ float  g_embed[N_CODE * D_DIM];// E row-major (gather)
__device__ float  g_esq[N_CODE];          // ||e||^2
__device__ unsigned long long g_key[N_TOK]; // packed (mono(dist)<<32 | code)

// ---------------- helpers ----------------------------------------------------
__device__ __forceinline__ uint32_t smem_u32(const void* p) {
    uint32_t a;
    asm("{ .reg .u64 t; cvta.to.shared.u64 t, %1; cvt.u32.u64 %0, t; }"
        : "=r"(a) : "l"(p));
    return a;
}
__device__ __forceinline__ uint32_t pack2(__half a, __half b) {
    __half2 h2 = __halves2half2(a, b);
    return *reinterpret_cast<uint32_t*>(&h2);
}
// monotone float->uint mapping (preserves total order)
__device__ __forceinline__ uint32_t fmono(float f) {
    uint32_t b = __float_as_uint(f);
    return b ^ ((b & 0x80000000u) ? 0xFFFFFFFFu : 0x80000000u);
}

#define MBAR_INIT(a, c) asm volatile("mbarrier.init.shared.b64 [%0], %1;" :: "r"(a), "r"((uint32_t)(c)) : "memory")
#define MBAR_EXPECT_TX(a, b) asm volatile("mbarrier.arrive.expect_tx.shared.b64 _, [%0], %1;" :: "r"(a), "r"((uint32_t)(b)) : "memory")
#define MBAR_ARRIVE(a)  asm volatile("mbarrier.arrive.shared.b64 _, [%0];" :: "r"(a) : "memory")

#define MBAR_WAIT(mbar, parity) do {                                          \
    uint32_t _m = (mbar), _ph = (parity), _done;                              \
    asm volatile("{ .reg .pred p; mbarrier.try_wait.parity.acquire.cta.shared::cta.b64 p, [%1], %2; selp.b32 %0, 1, 0, p; }" \
                 : "=r"(_done) : "r"(_m), "r"(_ph) : "memory");               \
    if (!_done) {                                                             \
        asm volatile("{ .reg .pred P1; WL_%=: mbarrier.try_wait.parity.acquire.cta.shared::cta.b64 P1, [%0], %1, 0x989680; @P1 bra.uni WD_%=; bra.uni WL_%=; WD_%=: }" \
                     :: "r"(_m), "r"(_ph) : "memory");                        \
    }                                                                         \
} while (0)

#define BULK_G2S(dst, src, bytes, mbar)                                       \
    asm volatile("cp.async.bulk.shared::cluster.global.mbarrier::complete_tx::bytes [%0], [%1], %2, [%3];" \
                 :: "r"(dst), "l"(src), "r"((uint32_t)(bytes)), "r"(mbar) : "memory")

// mma.sync m16n8k16 fp16 -> fp32 accumulate
__device__ __forceinline__ void mma_f16(float* d, const uint32_t* a, const uint32_t* b) {
    asm("mma.sync.aligned.m16n8k16.row.col.f32.f16.f16.f32 "
        "{%0,%1,%2,%3}, {%4,%5,%6,%7}, {%8,%9}, {%0,%1,%2,%3};"
        : "+f"(d[0]), "+f"(d[1]), "+f"(d[2]), "+f"(d[3])
        : "r"(a[0]), "r"(a[1]), "r"(a[2]), "r"(a[3]), "r"(b[0]), "r"(b[1]));
}

// ---------------------------------------------------------------------------
// Fused prep.
// Blocks [0, 1024): E prep, 2 codes per block (256 threads fully used).
// Blocks [1024, 2048): X split, one (m_block, chunk) fragment tile per block,
//   staged through shared memory so global stores are coalesced uint4 lines.
// ---------------------------------------------------------------------------
__global__ void __launch_bounds__(256) prep_all_kernel(const float* __restrict__ X,
                                                       const float* __restrict__ embed_sum,
                                                       const float* __restrict__ usage) {
    if (blockIdx.x < N_CODE / 2) {
        // -------- E prep: embed, esq, fp16 split in B-fragment order --------
        int t = threadIdx.x;
        int k = blockIdx.x * 2 + (t >> 7);
        int tl = t & 127;
        __shared__ float wsum[8];

        float u = fmaxf(usage[k], 1e-5f);
        float2 vv = ((const float2*)embed_sum)[k * 128 + tl];
        float v0 = vv.x / u, v1 = vv.y / u;
        ((float2*)g_embed)[k * 128 + tl] = make_float2(v0, v1);

        __half h0 = __float2half_rn(v0);
        __half l0 = __float2half_rn(v0 - __half2float(h0));
        __half h1 = __float2half_rn(v1);
        __half l1 = __float2half_rn(v1 - __half2float(h1));

        int d = 2 * tl;
        int pass = k >> 7, n_in = k & 127;
        int n_tile = n_in >> 3, ncol = n_in & 7;
        int ch = d >> 6, kk = d & 63, ks = kk >> 4, kc = kk & 15;
        int lane = ncol * 4 + ((kc >> 1) & 3);
        int reg = kc >> 3;
        int hbase = (pass * 4 + ch) * 8192 + ((ks * 16 + n_tile) * 32 + lane) * 4 + reg * 2;
        ((uint32_t*)g_ehi)[hbase >> 1] = pack2(h0, h1);
        ((uint32_t*)g_elo)[hbase >> 1] = pack2(l0, l1);

        // esq: warp reduce then 4 partials per code
        float val = v0 * v0 + v1 * v1;
        #pragma unroll
        for (int off = 16; off > 0; off >>= 1)
            val += __shfl_down_sync(0xffffffffu, val, off);
        if ((t & 31) == 0) wsum[t >> 5] = val;
        __syncthreads();
        if (tl == 0) {
            int w0 = (t >> 7) * 4;
            g_esq[k] = wsum[w0] + wsum[w0 + 1] + wsum[w0 + 2] + wsum[w0 + 3];
        }
    } else {
        // -------- X split staged via smem, coalesced output -----------------
        __shared__ uint32_t sh_hi[4096];   // 16 KB
        __shared__ uint32_t sh_lo[4096];   // 16 KB
        int tile = blockIdx.x - N_CODE / 2;     // 0..1023
        int m_block = tile >> 2, ch = tile & 3;
        int t = threadIdx.x;

        // g_key init (one tile per m_block does it)
        if (ch == 0 && t < 128) g_key[m_block * 128 + t] = 0xFFFFFFFFFFFFFFFFull;

        #pragma unroll
        for (int it = 0; it < 8; ++it) {
            int i4 = t + it * 256;                 // 0..2047 tile-local float4
            int tok_l = i4 >> 4;                   // 0..127
            int dl4 = i4 & 15;                     // float4 within 64-d chunk
            float4 x = ((const float4*)X)[(size_t)(m_block * 128 + tok_l) * 64 + ch * 16 + dl4];
            float xv[4] = {x.x, x.y, x.z, x.w};
            int m_tile = tok_l >> 4, r = tok_l & 15;
            #pragma unroll
            for (int j = 0; j < 4; j += 2) {
                __half ha = __float2half_rn(xv[j]);
                __half la = __float2half_rn(xv[j] - __half2float(ha));
                __half hb = __float2half_rn(xv[j + 1]);
                __half lb = __float2half_rn(xv[j + 1] - __half2float(hb));
                int kk = dl4 * 4 + j;              // 0..63 within chunk
                int ks = kk >> 4, kc = kk & 15;
                int lane = (r & 7) * 4 + ((kc >> 1) & 3);
                int reg = (r >> 3) | ((kc >> 3) << 1);
                int half_loc = ((ks * 8 + m_tile) * 32 + lane) * 8 + reg * 2;
                sh_hi[half_loc >> 1] = pack2(ha, hb);
                sh_lo[half_loc >> 1] = pack2(la, lb);
            }
        }
        __syncthreads();

        // coalesced copy out: 1024 uint4 per buffer
        uint4* dh = (uint4*)(((uint32_t*)g_xhi) + tile * 4096);
        uint4* dl = (uint4*)(((uint32_t*)g_xlo) + tile * 4096);
        const uint4* sh4 = (const uint4*)sh_hi;
        const uint4* sl4 = (const uint4*)sh_lo;
        #pragma unroll
        for (int it = 0; it < 4; ++it) {
            dh[t + it * 256] = sh4[t + it * 256];
            dl[t + it * 256] = sl4[t + it * 256];
        }
    }
}

// ---------------------------------------------------------------------------
// Fused fp16x2 mma.sync GEMM + argmin over an (m-tile 128, n-quarter 512) unit.
// Grid: 1024 CTAs = 256 m-tiles x 4 quarters. 288 threads = 8 compute + 1 prod.
// A (xhi+xlo, 128 KB) persistent in SMEM (loaded once); B rings through
// 3 x 32 KB stages. 4 passes x 128 codes, K=256 in 4 chunks of 64.
// SMEM: [0..64) mbarriers | [1024..3072) esq | [3072..134144) A | 3 B stages.
// ---------------------------------------------------------------------------
#define SMEM_TOTAL 232448
#define A_OFF 3072
#define B_OFF 134144

__global__ void __launch_bounds__(288, 1) argmin_mma_kernel() {
    extern __shared__ __align__(1024) char smem[];
    uint32_t sb = smem_u32(smem);
    int tid = threadIdx.x, lane = tid & 31, wid = tid >> 5;
    int mtile = blockIdx.x >> 2, q = blockIdx.x & 3;

    const uint32_t AF    = sb + 0;
    const uint32_t FB[3] = {sb + 8,  sb + 16, sb + 24};
    const uint32_t EB[3] = {sb + 32, sb + 40, sb + 48};
    float* esq_s = (float*)(smem + 1024);   // [512] quarter esq

    if (tid == 0) {
        MBAR_INIT(AF, 1);
        #pragma unroll
        for (int s = 0; s < 3; ++s) { MBAR_INIT(FB[s], 1); MBAR_INIT(EB[s], 8); }
    }
    for (int i = tid; i < 512; i += 288) esq_s[i] = g_esq[q * 512 + i];
    __syncthreads();

    int row0 = mtile * 128;

    if (wid == 8) {
        // ---------------- dedicated producer warp ---------------------------
        if (lane == 0) {
            // A: load once (4 chunks x (hi 16K + lo 16K))
            MBAR_EXPECT_TX(AF, 131072);
            #pragma unroll
            for (int ch = 0; ch < 4; ++ch) {
                BULK_G2S(sb + A_OFF + ch * 32768,
                         &g_xhi[(mtile * 4 + ch) * 8192], 16384, AF);
                BULK_G2S(sb + A_OFF + ch * 32768 + 16384,
                         &g_xlo[(mtile * 4 + ch) * 8192], 16384, AF);
            }
            // B stream: 16 chunk tiles
            #pragma unroll 1
            for (int g = 0; g < 16; ++g) {
                int s = g % 3;
                if (g >= 3) MBAR_WAIT(EB[s], ((g / 3) + 1) & 1);
                int pass = g >> 2, ch = g & 3;
                uint32_t st = sb + B_OFF + s * 32768;
                MBAR_EXPECT_TX(FB[s], 32768);
                BULK_G2S(st,         &g_ehi[((q * 4 + pass) * 4 + ch) * 8192], 16384, FB[s]);
                BULK_G2S(st + 16384, &g_elo[((q * 4 + pass) * 4 + ch) * 8192], 16384, FB[s]);
            }
        }
    } else {
        // ---------------- 8 compute warps ------------------------------------
        int warp_m = wid & 3, warp_n = wid >> 2;
        int t4 = lane & 3, g4 = lane >> 2;

        float best[2][2];
        int bestI[2][2];
        #pragma unroll
        for (int a = 0; a < 2; ++a)
            #pragma unroll
            for (int b = 0; b < 2; ++b) { best[a][b] = 3.4e38f; bestI[a][b] = 0; }

        MBAR_WAIT(AF, 0);   // A resident for whole kernel

        #pragma unroll 1
        for (int pass = 0; pass < 4; ++pass) {
            float acc[2][8][4];
            #pragma unroll
            for (int mt = 0; mt < 2; ++mt)
                #pragma unroll
                for (int nt = 0; nt < 8; ++nt)
                    #pragma unroll
                    for (int j = 0; j < 4; ++j) acc[mt][nt][j] = 0.f;

            #pragma unroll 1
            for (int ch = 0; ch < 4; ++ch) {
                int g = pass * 4 + ch;
                int s = g % 3;
                MBAR_WAIT(FB[s], (g / 3) & 1);

                const char* Ah = smem + A_OFF + ch * 32768;
                const char* Al = Ah + 16384;
                const char* Bh = smem + B_OFF + s * 32768;
                const char* Bl = Bh + 16384;

                #pragma unroll
                for (int ks = 0; ks < 4; ++ks) {
                    uint32_t ah[2][4], al[2][4];
                    #pragma unroll
                    for (int mt = 0; mt < 2; ++mt) {
                        int off = ((ks * 8 + warp_m * 2 + mt) * 32 + lane) * 16;
                        *(uint4*)ah[mt] = *(const uint4*)(Ah + off);
                        *(uint4*)al[mt] = *(const uint4*)(Al + off);
                    }
                    uint32_t bh[8][2], bl[8][2];
                    #pragma unroll
                    for (int nt = 0; nt < 8; ++nt) {
                        int off = ((ks * 16 + warp_n * 8 + nt) * 32 + lane) * 8;
                        *(uint2*)bh[nt] = *(const uint2*)(Bh + off);
                        *(uint2*)bl[nt] = *(const uint2*)(Bl + off);
                    }
                    // term-ordered: hi*hi, hi*lo, lo*hi
                    #pragma unroll
                    for (int mt = 0; mt < 2; ++mt)
                        #pragma unroll
                        for (int nt = 0; nt < 8; ++nt)
                            mma_f16(acc[mt][nt], ah[mt], bh[nt]);
                    #pragma unroll
                    for (int mt = 0; mt < 2; ++mt)
                        #pragma unroll
                        for (int nt = 0; nt < 8; ++nt)
                            mma_f16(acc[mt][nt], ah[mt], bl[nt]);
                    #pragma unroll
                    for (int mt = 0; mt < 2; ++mt)
                        #pragma unroll
                        for (int nt = 0; nt < 8; ++nt)
                            mma_f16(acc[mt][nt], al[mt], bh[nt]);
                }
                if (lane == 0) MBAR_ARRIVE(EB[s]);
            }

            // fold pass into running argmin: dist = esq - 2*dot
            #pragma unroll
            for (int nt = 0; nt < 8; ++nt) {
                int clocal = pass * 128 + warp_n * 64 + nt * 8 + 2 * t4;
                float e0 = esq_s[clocal], e1 = esq_s[clocal + 1];
                int cbase = q * 512 + clocal;
                #pragma unroll
                for (int mt = 0; mt < 2; ++mt) {
                    float d0v = fmaf(-2.f, acc[mt][nt][0], e0);
                    if (d0v < best[mt][0]) { best[mt][0] = d0v; bestI[mt][0] = cbase; }
                    float d1v = fmaf(-2.f, acc[mt][nt][1], e1);
                    if (d1v < best[mt][0]) { best[mt][0] = d1v; bestI[mt][0] = cbase + 1; }
                    float d2v = fmaf(-2.f, acc[mt][nt][2], e0);
                    if (d2v < best[mt][1]) { best[mt][1] = d2v; bestI[mt][1] = cbase; }
                    float d3v = fmaf(-2.f, acc[mt][nt][3], e1);
                    if (d3v < best[mt][1]) { best[mt][1] = d3v; bestI[mt][1] = cbase + 1; }
                }
            }
        }

        // width-4 shuffle reduce, then global atomic merge
        #pragma unroll
        for (int mt = 0; mt < 2; ++mt)
            #pragma unroll
            for (int h = 0; h < 2; ++h) {
                float b = best[mt][h];
                int bi = bestI[mt][h];
                #pragma unroll
                for (int off = 2; off > 0; off >>= 1) {
                    float ob = __shfl_down_sync(0xffffffffu, b, off, 4);
                    int obi = __shfl_down_sync(0xffffffffu, bi, off, 4);
                    if (ob < b || (ob == b && obi < bi)) { b = ob; bi = obi; }
                }
                if (t4 == 0) {
                    int tok = row0 + warp_m * 32 + mt * 16 + g4 + 8 * h;
                    unsigned long long key =
                        ((unsigned long long)fmono(b) << 32) | (uint32_t)bi;
                    atomicMin(&g_key[tok], key);
                }
            }
    }
}

// ---------------------------------------------------------------------------
// gather: one thread per (token, float4 chunk). 8192 CTAs x 256 threads.
// ---------------------------------------------------------------------------
__global__ void __launch_bounds__(256) gather_kernel(float* __restrict__ out, int N) {
    int i = blockIdx.x * 256 + threadIdx.x;     // [0, N*64)
    int tok = i >> 6, c4 = i & 63;
    int idx = (int)(g_key[tok] & 0xFFFFFFFFull);
    float4 v = ((const float4*)g_embed)[(size_t)idx * 64 + c4];
    ((float4*)out)[i] = v;
    if (c4 == 0) out[(size_t)N * D_DIM + tok] = (float)idx;
}

// ---------------------------------------------------------------------------
extern "C" void kernel_launch(void* const* d_in, const int* in_sizes, int n_in,
                              void* d_out, int out_size) {
    const float* X  = (const float*)d_in[0];
    const float* ES = (const float*)d_in[1];
    const float* U  = (const float*)d_in[2];
    float* out = (float*)d_out;
    (void)n_in; (void)out_size;
    int N = in_sizes[0] / D_DIM;   // 32768

    cudaFuncSetAttribute(argmin_mma_kernel,
                         cudaFuncAttributeMaxDynamicSharedMemorySize, SMEM_TOTAL);

    prep_all_kernel<<<N_CODE / 2 + (N / 128) * 4, 256>>>(X, ES, U);
    argmin_mma_kernel<<<(N / 128) * 4, 288, SMEM_TOTAL>>>();
    gather_kernel<<<(N * 64) / 256, 256>>>(out, N);
}